// round 2
// baseline (speedup 1.0000x reference)
#include <cuda_runtime.h>
#include <cstdint>

// Problem constants
#define BB   64      // batch
#define TT   1024    // time steps
#define HH   256     // hidden per direction
#define DIN  136     // input features (68*2)
#define G4   1024    // 4*H
#define NBLK 64      // persistent blocks per direction
#define HB   (HH*BB) // 16384 floats of hidden state per direction

// ---------------- scratch (device globals; no allocations allowed) ----------------
__device__ __align__(16) float g_proj[2][(size_t)TT * G4 * BB]; // [dir][t][row][b]  2*256MB
__device__ __align__(16) float g_hs[(size_t)TT * 2 * HH * BB];  // [t][dir*H+j][b]   128MB
__device__ __align__(16) float g_hbuf[2][2][HB];                // [dir][parity][j][b]
__device__ unsigned g_bar_arrive[2];
__device__ unsigned g_bar_epoch[2];

// ---------------- activations (fast, ~1e-6 rel err — fine vs 1e-3) ----------------
__device__ __forceinline__ float sigf(float x) {
    return 1.0f / (1.0f + __expf(-x));
}
__device__ __forceinline__ float tanh_fast(float x) {
    float xx = fminf(fmaxf(x, -10.0f), 10.0f);
    float e = __expf(2.0f * xx);
    return (e - 1.0f) / (e + 1.0f);
}

// ---------------- init: reset mutable state each launch (graph-replay safe) -------
__global__ void init_kernel() {
    int tid = threadIdx.x;
    float* hb = &g_hbuf[0][0][0];
    for (int i = tid; i < 2 * 2 * HB; i += 256) hb[i] = 0.0f;
    if (tid < 2) { g_bar_arrive[tid] = 0u; g_bar_epoch[tid] = 0u; }
}

// ---------------- input projection GEMM ----------------
// proj[dir][t][row][b] = b_ih[row] + sum_k x[b][t][k] * w_ih[row][k]
// grid (16 row-tiles, T, 2 dirs), 128 threads, tile 64 rows x 64 b, thread 8r x 4b.
__global__ void __launch_bounds__(128, 2) proj_kernel(
    const float* __restrict__ x,
    const float* __restrict__ wih_f, const float* __restrict__ wih_b,
    const float* __restrict__ bih_f, const float* __restrict__ bih_b)
{
    extern __shared__ float sm[];
    float* xs = sm;               // [136][68] transposed: xs[k][b]
    float* ws = sm + 136 * 68;    // [136][68] transposed: ws[k][r]

    const int t   = blockIdx.y;
    const int dir = blockIdx.z;
    const int r0  = blockIdx.x * 64;
    const float* w  = dir ? wih_b : wih_f;
    const float* bi = dir ? bih_b : bih_f;
    const int tid = threadIdx.x;

    // load x tile (64 rows of 136 floats) transposed into SMEM
    for (int i = tid; i < 64 * 34; i += 128) {
        int b = i / 34, k4 = i - b * 34;
        float4 v = __ldg(((const float4*)(x + ((size_t)b * TT + t) * DIN)) + k4);
        int kb = k4 * 4;
        xs[(kb + 0) * 68 + b] = v.x;
        xs[(kb + 1) * 68 + b] = v.y;
        xs[(kb + 2) * 68 + b] = v.z;
        xs[(kb + 3) * 68 + b] = v.w;
    }
    // load w tile (64 rows of 136 floats) transposed into SMEM
    for (int i = tid; i < 64 * 34; i += 128) {
        int r = i / 34, k4 = i - r * 34;
        float4 v = __ldg(((const float4*)(w + (size_t)(r0 + r) * DIN)) + k4);
        int kb = k4 * 4;
        ws[(kb + 0) * 68 + r] = v.x;
        ws[(kb + 1) * 68 + r] = v.y;
        ws[(kb + 2) * 68 + r] = v.z;
        ws[(kb + 3) * 68 + r] = v.w;
    }
    __syncthreads();

    const int tx = tid & 15;   // b-group: b = tx*4 .. +3
    const int ty = tid >> 4;   // r-group: r = ty*8 .. +7
    float acc[8][4];
#pragma unroll
    for (int q = 0; q < 8; q++)
#pragma unroll
        for (int j = 0; j < 4; j++) acc[q][j] = 0.0f;

#pragma unroll 4
    for (int k = 0; k < DIN; k++) {
        float4 xv = *(const float4*)(xs + k * 68 + tx * 4);
        float4 w0 = *(const float4*)(ws + k * 68 + ty * 8);
        float4 w1 = *(const float4*)(ws + k * 68 + ty * 8 + 4);
        float wv[8] = {w0.x, w0.y, w0.z, w0.w, w1.x, w1.y, w1.z, w1.w};
#pragma unroll
        for (int q = 0; q < 8; q++) {
            acc[q][0] += wv[q] * xv.x;
            acc[q][1] += wv[q] * xv.y;
            acc[q][2] += wv[q] * xv.z;
            acc[q][3] += wv[q] * xv.w;
        }
    }

    float* dst = g_proj[dir] + (size_t)t * G4 * BB;
#pragma unroll
    for (int q = 0; q < 8; q++) {
        int row = r0 + ty * 8 + q;
        float bias = __ldg(bi + row);
        float4 o = make_float4(acc[q][0] + bias, acc[q][1] + bias,
                               acc[q][2] + bias, acc[q][3] + bias);
        *(float4*)(dst + (size_t)row * BB + tx * 4) = o;
    }
}

// ---------------- persistent recurrent scan ----------------
// 128 blocks (64 fwd + 64 bwd), 256 threads each, one CTA per SM.
// Block owns j' in [j0, j0+4): 16 W_hh rows held in registers (k-sliced per warp).
__global__ void __launch_bounds__(256, 1) scan_kernel(
    const float* __restrict__ whh_f, const float* __restrict__ whh_b,
    const float* __restrict__ bhh_f, const float* __restrict__ bhh_b)
{
    extern __shared__ float smem[];
    float* h_s = smem;           // [256][64]  transposed h: h_s[k][b]  (64KB)
    float* red = smem + HB;      // [8][16][64] split-k partials         (32KB)

    const int dir = blockIdx.x >> 6;
    const int blk = blockIdx.x & 63;
    const int j0  = blk * 4;
    const float* whh = dir ? whh_b : whh_f;
    const float* bhh = dir ? bhh_b : bhh_f;
    const int tid = threadIdx.x;

    // compute-phase mapping: warp = k-slice, lanes = 8 b-groups x 4 gates
    const int bg = tid & 7;          // b = bg*8 .. +7
    const int rg = (tid >> 3) & 3;   // gate index (rows rg*4..+3 local)
    const int ks = tid >> 5;         // k in [ks*32, ks*32+32)

    // W_hh registers: w[q][kk] = w_hh[gate*256 + j0 + q][ks*32 + kk]
    float w[4][32];
#pragma unroll
    for (int q = 0; q < 4; q++) {
        int row = rg * 256 + j0 + q;
#pragma unroll
        for (int kk = 0; kk < 32; kk++)
            w[q][kk] = __ldg(whh + (size_t)row * HH + ks * 32 + kk);
    }

    // gate/state-phase mapping: thread owns (jj2, b2); c stays in a register
    const int jj2 = tid >> 6;        // 0..3
    const int b2  = tid & 63;        // 0..63
    float bh[4];
#pragma unroll
    for (int g = 0; g < 4; g++) bh[g] = __ldg(bhh + g * 256 + j0 + jj2);

    float c = 0.0f;
    int p = 0;
    float* hbuf = &g_hbuf[dir][0][0];

    for (int s = 0; s < TT; ++s) {
        const int t = dir ? (TT - 1 - s) : s;

        // prefetch x-projection for this thread's 4 gate values (overlaps k-loop)
        float pf[4];
#pragma unroll
        for (int g = 0; g < 4; g++)
            pf[g] = __ldg(g_proj[dir] + ((size_t)t * G4 + g * 256 + j0 + jj2) * BB + b2);

        // pull h_prev (written by all 64 blocks of this dir) into SMEM; L2-coherent loads
        {
            const float4* src = (const float4*)(hbuf + p * HB);
            float4* dst = (float4*)h_s;
#pragma unroll
            for (int i = 0; i < 16; i++)
                dst[tid + (i << 8)] = __ldcg(src + tid + (i << 8));
        }
        __syncthreads();

        // k-slice GEMM: acc[q][i] = sum_{k in slice} w[q][k] * h[bg*8+i][k]
        float acc[4][8];
#pragma unroll
        for (int q = 0; q < 4; q++)
#pragma unroll
            for (int i = 0; i < 8; i++) acc[q][i] = 0.0f;

#pragma unroll
        for (int kk = 0; kk < 32; kk++) {
            const float4* h4 = (const float4*)(h_s + ((ks << 5) + kk) * 64 + (bg << 3));
            float4 a = h4[0];
            float4 b4 = h4[1];
#pragma unroll
            for (int q = 0; q < 4; q++) {
                float wq = w[q][kk];
                acc[q][0] += wq * a.x;  acc[q][1] += wq * a.y;
                acc[q][2] += wq * a.z;  acc[q][3] += wq * a.w;
                acc[q][4] += wq * b4.x; acc[q][5] += wq * b4.y;
                acc[q][6] += wq * b4.z; acc[q][7] += wq * b4.w;
            }
        }

        // write split-k partials: red[ks][gate*4+q][b]
#pragma unroll
        for (int q = 0; q < 4; q++) {
            float* rp = red + ((ks << 4) + (rg << 2) + q) * 64 + (bg << 3);
            *(float4*)(rp)     = make_float4(acc[q][0], acc[q][1], acc[q][2], acc[q][3]);
            *(float4*)(rp + 4) = make_float4(acc[q][4], acc[q][5], acc[q][6], acc[q][7]);
        }
        __syncthreads();

        // gate phase: reduce 8 partials per gate, apply LSTM cell
        float gv[4];
#pragma unroll
        for (int g = 0; g < 4; g++) {
            float v = pf[g] + bh[g];
#pragma unroll
            for (int wi = 0; wi < 8; wi++)
                v += red[((wi << 4) + (g << 2) + jj2) * 64 + b2];
            gv[g] = v;
        }
        float i_ = sigf(gv[0]);
        float f_ = sigf(gv[1]);
        float g_ = tanh_fast(gv[2]);
        float o_ = sigf(gv[3]);
        c = f_ * c + i_ * g_;
        float h = o_ * tanh_fast(c);

        // publish h for next step + store hidden sequence
        hbuf[(p ^ 1) * HB + (j0 + jj2) * 64 + b2] = h;
        g_hs[((size_t)t * 512 + dir * HH + j0 + jj2) * BB + b2] = h;

        // direction-local grid barrier (monotonic epochs, no reset mid-run)
        __syncthreads();
        if (tid == 0) {
            __threadfence();
            unsigned ticket = atomicAdd(&g_bar_arrive[dir], 1u);
            if (ticket == (unsigned)(s + 1) * NBLK - 1u) {
                atomicExch(&g_bar_epoch[dir], (unsigned)(s + 1));
            } else {
                volatile unsigned* ep = &g_bar_epoch[dir];
                while (*ep <= (unsigned)s) { }
            }
            __threadfence();
        }
        __syncthreads();
        p ^= 1;
    }
}

// ---------------- final FC: out[b][t][o] = sum_j hs[t][j][b]*fc_w[o][j] + fc_b[o] ---
__global__ void __launch_bounds__(320) fc_kernel(
    const float* __restrict__ fcw, const float* __restrict__ fcb,
    float* __restrict__ out)
{
    const int t = blockIdx.x;
    const int o = threadIdx.x / 64;  // 0..4
    const int b = threadIdx.x & 63;  // 0..63
    const float* hp = g_hs + (size_t)t * 512 * BB + b;
    const float* wp = fcw + o * 512;
    float acc = 0.0f;
#pragma unroll 8
    for (int j = 0; j < 512; j++)
        acc += hp[(size_t)j * BB] * __ldg(wp + j);
    out[((size_t)b * TT + t) * 5 + o] = acc + __ldg(fcb + o);
}

// ---------------- launch ----------------
extern "C" void kernel_launch(void* const* d_in, const int* in_sizes, int n_in,
                              void* d_out, int out_size)
{
    const float* x      = (const float*)d_in[0];
    const float* wih_f  = (const float*)d_in[1];
    const float* whh_f  = (const float*)d_in[2];
    const float* bih_f  = (const float*)d_in[3];
    const float* bhh_f  = (const float*)d_in[4];
    const float* wih_b  = (const float*)d_in[5];
    const float* whh_b  = (const float*)d_in[6];
    const float* bih_b  = (const float*)d_in[7];
    const float* bhh_b  = (const float*)d_in[8];
    const float* fcw    = (const float*)d_in[9];
    const float* fcb    = (const float*)d_in[10];
    float* out = (float*)d_out;

    const int proj_smem = 2 * 136 * 68 * (int)sizeof(float);   // 73,984 B
    const int scan_smem = (HB + 8 * 16 * 64) * (int)sizeof(float); // 98,304 B
    cudaFuncSetAttribute(proj_kernel, cudaFuncAttributeMaxDynamicSharedMemorySize, proj_smem);
    cudaFuncSetAttribute(scan_kernel, cudaFuncAttributeMaxDynamicSharedMemorySize, scan_smem);

    init_kernel<<<1, 256>>>();

    dim3 pg(16, TT, 2);
    proj_kernel<<<pg, 128, proj_smem>>>(x, wih_f, wih_b, bih_f, bih_b);

    scan_kernel<<<2 * NBLK, 256, scan_smem>>>(whh_f, whh_b, bhh_f, bhh_b);

    fc_kernel<<<TT, 320>>>(fcw, fcb, out);
}